// round 3
// baseline (speedup 1.0000x reference)
#include <cuda_runtime.h>

#define D_MODEL 768
#define NHEADS  12
#define DK      64
#define BATCH   2
#define SEQ     2048
#define MTOT    (BATCH*SEQ)   // 4096

// Scratch (device globals: allocation-free, harness-safe)
__device__ float g_q [BATCH*NHEADS*SEQ*DK];   // [B,H,S,dk]
__device__ float g_k [BATCH*NHEADS*SEQ*DK];
__device__ float g_v [BATCH*NHEADS*SEQ*DK];
__device__ float g_ao[MTOT*D_MODEL];          // [B,S,D] attention output

#define BM 64
#define BN 64
#define BK 16

// mode 0/1/2: write head-split into g_q/g_k/g_v.  mode 3: plain row-major to outp.
// A==nullptr -> read from g_ao (final projection).
__global__ __launch_bounds__(256) void gemm_bias_kernel(
        const float* __restrict__ A, const float* __restrict__ W,
        const float* __restrict__ bias, float* __restrict__ outp, int mode) {
    __shared__ float As[BK][BM];
    __shared__ float Bs[BK][BN];
    const float* __restrict__ Ain = A ? A : (const float*)g_ao;

    const int m0 = blockIdx.x * BM;
    const int n0 = blockIdx.y * BN;
    const int t  = threadIdx.x;

    const int tm = (t >> 4) * 4;   // 0..60
    const int tn = (t & 15) * 4;   // 0..60

    const int lm  = t >> 2;        // A-load: row 0..63
    const int lk  = (t & 3) * 4;   // A-load: k offset 0,4,8,12
    const int lbk = t >> 4;        // B-load: k row 0..15
    const int lbn = (t & 15) * 4;  // B-load: n offset

    float acc[4][4] = {};

    for (int k0 = 0; k0 < D_MODEL; k0 += BK) {
        float4 av = *(const float4*)&Ain[(m0 + lm) * D_MODEL + k0 + lk];
        As[lk+0][lm] = av.x; As[lk+1][lm] = av.y;
        As[lk+2][lm] = av.z; As[lk+3][lm] = av.w;
        *(float4*)&Bs[lbk][lbn] =
            *(const float4*)&W[(k0 + lbk) * D_MODEL + n0 + lbn];
        __syncthreads();

        #pragma unroll
        for (int kk = 0; kk < BK; kk++) {
            float4 a4 = *(const float4*)&As[kk][tm];
            float4 b4 = *(const float4*)&Bs[kk][tn];
            float av_[4] = {a4.x, a4.y, a4.z, a4.w};
            float bv_[4] = {b4.x, b4.y, b4.z, b4.w};
            #pragma unroll
            for (int i = 0; i < 4; i++)
                #pragma unroll
                for (int j = 0; j < 4; j++)
                    acc[i][j] += av_[i] * bv_[j];
        }
        __syncthreads();
    }

    float bb[4];
    #pragma unroll
    for (int j = 0; j < 4; j++) bb[j] = bias[n0 + tn + j];

    #pragma unroll
    for (int i = 0; i < 4; i++) {
        const int m = m0 + tm + i;
        float4 r;
        r.x = acc[i][0] + bb[0];
        r.y = acc[i][1] + bb[1];
        r.z = acc[i][2] + bb[2];
        r.w = acc[i][3] + bb[3];
        if (mode == 3) {
            *(float4*)&outp[(size_t)m * D_MODEL + n0 + tn] = r;
        } else {
            float* o = (mode == 0) ? g_q : (mode == 1) ? g_k : g_v;
            const int n  = n0 + tn;
            const int b  = m >> 11;      // /2048
            const int s  = m & 2047;
            const int h  = n >> 6;       // /64
            const int dd = n & 63;
            *(float4*)&o[(((size_t)(b * NHEADS + h) * SEQ) + s) * DK + dd] = r;
        }
    }
}

// Flash attention: one block = 64 queries of one (b,h). 256 threads = 4/row.
__global__ __launch_bounds__(256) void flash_attn_kernel() {
    __shared__ float Ks[64][68];   // pad 68: stride 272B -> conflict-free QK^T reads
    __shared__ float Vs[64][68];

    const int qt = blockIdx.x, h = blockIdx.y, b = blockIdx.z;
    const int t    = threadIdx.x;
    const int row  = t >> 2;     // query row in tile, 0..63
    const int cg   = t & 3;      // column group
    const int lane = t & 31;

    const size_t headBase = (size_t)(b * NHEADS + h) * SEQ * DK;
    const float* __restrict__ qp = g_q + headBase + (size_t)(qt * 64 + row) * DK;
    const float* __restrict__ kp = g_k + headBase;
    const float* __restrict__ vp = g_v + headBase;

    float qreg[64];
    #pragma unroll
    for (int d = 0; d < 64; d += 4) {
        float4 v4 = *(const float4*)&qp[d];
        qreg[d+0] = v4.x; qreg[d+1] = v4.y; qreg[d+2] = v4.z; qreg[d+3] = v4.w;
    }

    float o[16] = {};            // this thread owns output dims cg*16 .. cg*16+15
    float mmax = -1e30f, lsum = 0.f;

    for (int k0 = 0; k0 < SEQ; k0 += 64) {
        #pragma unroll
        for (int i = 0; i < 4; i++) {
            int fi = t + i * 256;            // float4 index 0..1023
            int r  = fi >> 4;
            int c  = (fi & 15) * 4;
            *(float4*)&Ks[r][c] = *(const float4*)&kp[(size_t)(k0 + r) * DK + c];
            *(float4*)&Vs[r][c] = *(const float4*)&vp[(size_t)(k0 + r) * DK + c];
        }
        __syncthreads();

        // S = Q K^T for 16 keys per thread (col = j*4 + cg -> conflict-free)
        float s[16];
        #pragma unroll
        for (int j = 0; j < 16; j++) {
            const int col = j * 4 + cg;
            float acc = 0.f;
            #pragma unroll
            for (int d = 0; d < 64; d += 4) {
                float4 kv = *(const float4*)&Ks[col][d];
                acc += qreg[d+0]*kv.x + qreg[d+1]*kv.y
                     + qreg[d+2]*kv.z + qreg[d+3]*kv.w;
            }
            s[j] = acc * 0.125f;   // 1/sqrt(64)
        }

        // online softmax (row spread across 4 lanes)
        float tmax = s[0];
        #pragma unroll
        for (int j = 1; j < 16; j++) tmax = fmaxf(tmax, s[j]);
        tmax = fmaxf(tmax, __shfl_xor_sync(0xffffffffu, tmax, 1));
        tmax = fmaxf(tmax, __shfl_xor_sync(0xffffffffu, tmax, 2));
        const float nmax = fmaxf(mmax, tmax);
        const float corr = __expf(mmax - nmax);

        float ps = 0.f;
        #pragma unroll
        for (int j = 0; j < 16; j++) { s[j] = __expf(s[j] - nmax); ps += s[j]; }
        ps += __shfl_xor_sync(0xffffffffu, ps, 1);
        ps += __shfl_xor_sync(0xffffffffu, ps, 2);
        lsum = lsum * corr + ps;
        mmax = nmax;

        #pragma unroll
        for (int i = 0; i < 16; i++) o[i] *= corr;

        // O += P V : p values exchanged via shfl (no P smem tile needed)
        const int srcbase = lane & ~3;
        #pragma unroll
        for (int j = 0; j < 64; j++) {
            float p = __shfl_sync(0xffffffffu, s[j >> 2], srcbase | (j & 3));
            #pragma unroll
            for (int d = 0; d < 16; d += 4) {
                float4 vv = *(const float4*)&Vs[j][cg * 16 + d];
                o[d+0] += p * vv.x; o[d+1] += p * vv.y;
                o[d+2] += p * vv.z; o[d+3] += p * vv.w;
            }
        }
        __syncthreads();
    }

    const float inv = 1.0f / lsum;
    const int srow = qt * 64 + row;
    float* op = g_ao + (size_t)(b * SEQ + srow) * D_MODEL + h * DK + cg * 16;
    #pragma unroll
    for (int d = 0; d < 16; d += 4) {
        float4 r;
        r.x = o[d+0]*inv; r.y = o[d+1]*inv; r.z = o[d+2]*inv; r.w = o[d+3]*inv;
        *(float4*)&op[d] = r;
    }
}

extern "C" void kernel_launch(void* const* d_in, const int* in_sizes, int n_in,
                              void* d_out, int out_size) {
    const float* q  = (const float*)d_in[0];
    const float* k  = (const float*)d_in[1];
    const float* v  = (const float*)d_in[2];
    const float* Wq = (const float*)d_in[3];
    const float* bq = (const float*)d_in[4];
    const float* Wk = (const float*)d_in[5];
    const float* bk = (const float*)d_in[6];
    const float* Wv = (const float*)d_in[7];
    const float* bv = (const float*)d_in[8];
    const float* Wo = (const float*)d_in[9];
    const float* bo = (const float*)d_in[10];
    float* out = (float*)d_out;

    dim3 gp(MTOT / BM, D_MODEL / BN);     // 64 x 12
    gemm_bias_kernel<<<gp, 256>>>(q, Wq, bq, nullptr, 0);
    gemm_bias_kernel<<<gp, 256>>>(k, Wk, bk, nullptr, 1);
    gemm_bias_kernel<<<gp, 256>>>(v, Wv, bv, nullptr, 2);

    dim3 ga(SEQ / 64, NHEADS, BATCH);     // 32 x 12 x 2
    flash_attn_kernel<<<ga, 256>>>();

    gemm_bias_kernel<<<gp, 256>>>(nullptr, Wo, bo, out, 3);
}

// round 4
// speedup vs baseline: 3.4188x; 3.4188x over previous
#include <cuda_runtime.h>
#include <cstdint>

#define D_MODEL 768
#define NHEADS  12
#define DK      64
#define BATCH   2
#define SEQ     2048
#define MTOT    (BATCH*SEQ)   // 4096

// Scratch (device globals: allocation-free, harness-safe)
__device__ float g_q [BATCH*NHEADS*SEQ*DK];   // [B,H,S,dk]
__device__ float g_k [BATCH*NHEADS*SEQ*DK];
__device__ float g_v [BATCH*NHEADS*SEQ*DK];
__device__ float g_ao[MTOT*D_MODEL];          // [B,S,D] attention output

#define BM 64
#define BN 64
#define BK 16

// ---------------------------------------------------------------------------
// fp32 SIMT GEMM with bias (exact) — unchanged from R1 (proven correct)
// ---------------------------------------------------------------------------
__global__ __launch_bounds__(256) void gemm_bias_kernel(
        const float* __restrict__ A, const float* __restrict__ W,
        const float* __restrict__ bias, float* __restrict__ outp, int mode) {
    __shared__ float As[BK][BM];
    __shared__ float Bs[BK][BN];
    const float* __restrict__ Ain = A ? A : (const float*)g_ao;

    const int m0 = blockIdx.x * BM;
    const int n0 = blockIdx.y * BN;
    const int t  = threadIdx.x;

    const int tm = (t >> 4) * 4;
    const int tn = (t & 15) * 4;

    const int lm  = t >> 2;
    const int lk  = (t & 3) * 4;
    const int lbk = t >> 4;
    const int lbn = (t & 15) * 4;

    float acc[4][4] = {};

    for (int k0 = 0; k0 < D_MODEL; k0 += BK) {
        float4 av = *(const float4*)&Ain[(m0 + lm) * D_MODEL + k0 + lk];
        As[lk+0][lm] = av.x; As[lk+1][lm] = av.y;
        As[lk+2][lm] = av.z; As[lk+3][lm] = av.w;
        *(float4*)&Bs[lbk][lbn] =
            *(const float4*)&W[(k0 + lbk) * D_MODEL + n0 + lbn];
        __syncthreads();

        #pragma unroll
        for (int kk = 0; kk < BK; kk++) {
            float4 a4 = *(const float4*)&As[kk][tm];
            float4 b4 = *(const float4*)&Bs[kk][tn];
            float av_[4] = {a4.x, a4.y, a4.z, a4.w};
            float bv_[4] = {b4.x, b4.y, b4.z, b4.w};
            #pragma unroll
            for (int i = 0; i < 4; i++)
                #pragma unroll
                for (int j = 0; j < 4; j++)
                    acc[i][j] += av_[i] * bv_[j];
        }
        __syncthreads();
    }

    float bb[4];
    #pragma unroll
    for (int j = 0; j < 4; j++) bb[j] = bias[n0 + tn + j];

    #pragma unroll
    for (int i = 0; i < 4; i++) {
        const int m = m0 + tm + i;
        float4 r;
        r.x = acc[i][0] + bb[0];
        r.y = acc[i][1] + bb[1];
        r.z = acc[i][2] + bb[2];
        r.w = acc[i][3] + bb[3];
        if (mode == 3) {
            *(float4*)&outp[(size_t)m * D_MODEL + n0 + tn] = r;
        } else {
            float* o = (mode == 0) ? g_q : (mode == 1) ? g_k : g_v;
            const int n  = n0 + tn;
            const int b  = m >> 11;
            const int s  = m & 2047;
            const int h  = n >> 6;
            const int dd = n & 63;
            *(float4*)&o[(((size_t)(b * NHEADS + h) * SEQ) + s) * DK + dd] = r;
        }
    }
}

// ---------------------------------------------------------------------------
// Tensor-core (tf32 HMMA) flash attention
// Block: 128 queries of one (b,h); 8 warps, each warp owns 16 query rows.
// ---------------------------------------------------------------------------
#define KPAD 68   // bank: (4*key + d) % 32 -> conflict-free for QK B-frags
#define VPAD 72   // bank: (8*key + d) % 32 -> conflict-free for PV B-frags
#define PPAD 68

__device__ __forceinline__ uint32_t f2tf32(float x) {
    uint32_t r;
    asm("cvt.rna.tf32.f32 %0, %1;" : "=r"(r) : "f"(x));
    return r;
}
__device__ __forceinline__ float fexp2(float x) {
    float y;
    asm("ex2.approx.ftz.f32 %0, %1;" : "=f"(y) : "f"(x));
    return y;
}
__device__ __forceinline__ void mma_tf32(float c[4],
        uint32_t a0, uint32_t a1, uint32_t a2, uint32_t a3,
        uint32_t b0, uint32_t b1) {
    asm volatile(
        "mma.sync.aligned.m16n8k8.row.col.f32.tf32.tf32.f32 "
        "{%0,%1,%2,%3}, {%4,%5,%6,%7}, {%8,%9}, {%0,%1,%2,%3};"
        : "+f"(c[0]), "+f"(c[1]), "+f"(c[2]), "+f"(c[3])
        : "r"(a0), "r"(a1), "r"(a2), "r"(a3), "r"(b0), "r"(b1));
}

__global__ __launch_bounds__(256) void flash_attn_tc() {
    extern __shared__ uint32_t smem_u[];
    uint32_t* Ksu = smem_u;                       // [64][KPAD]
    uint32_t* Vsu = smem_u + 64 * KPAD;           // [64][VPAD]
    float*    Psb = (float*)(smem_u + 64 * KPAD + 64 * VPAD); // 8 x [16][PPAD]

    const int t    = threadIdx.x;
    const int warp = t >> 5;
    const int lane = t & 31;
    const int g    = lane >> 2;   // group id (row within 16, col group)
    const int tig  = lane & 3;    // thread in group

    const int qt = blockIdx.x, h = blockIdx.y, b = blockIdx.z;
    const size_t headBase = (size_t)(b * NHEADS + h) * SEQ * DK;
    const float* __restrict__ kp = g_k + headBase;
    const float* __restrict__ vp = g_v + headBase;

    // ---- load Q fragments (held in regs all kernel), scale folded in ----
    // scale = 1/sqrt(64) * log2(e)  (softmax done in base 2)
    const float qscale = 0.125f * 1.4426950408889634f;
    const int row_a = qt * 128 + warp * 16 + g;   // global query row (lo half)
    const float* __restrict__ qa = g_q + headBase + (size_t)row_a * DK;
    const float* __restrict__ qb = qa + 8 * DK;   // +8 rows (hi half)

    uint32_t qf[8][4];
    #pragma unroll
    for (int ks = 0; ks < 8; ks++) {
        const int c0 = 8 * ks + tig;
        qf[ks][0] = f2tf32(qa[c0]     * qscale);
        qf[ks][1] = f2tf32(qb[c0]     * qscale);
        qf[ks][2] = f2tf32(qa[c0 + 4] * qscale);
        qf[ks][3] = f2tf32(qb[c0 + 4] * qscale);
    }

    float o[8][4];
    #pragma unroll
    for (int nt = 0; nt < 8; nt++)
        #pragma unroll
        for (int c = 0; c < 4; c++) o[nt][c] = 0.f;
    float m0 = -1e30f, m1 = -1e30f, l0 = 0.f, l1 = 0.f;

    float* Pw = Psb + warp * 16 * PPAD;

    for (int k0 = 0; k0 < SEQ; k0 += 64) {
        // ---- load K/V tile, converting to tf32 at store ----
        #pragma unroll
        for (int i = 0; i < 4; i++) {
            const int fi = t + i * 256;     // 0..1023 float4 slots
            const int r  = fi >> 4;
            const int c  = (fi & 15) * 4;
            float4 kv = *(const float4*)&kp[(size_t)(k0 + r) * DK + c];
            float4 vv = *(const float4*)&vp[(size_t)(k0 + r) * DK + c];
            uint4 ku = { f2tf32(kv.x), f2tf32(kv.y), f2tf32(kv.z), f2tf32(kv.w) };
            uint4 vu = { f2tf32(vv.x), f2tf32(vv.y), f2tf32(vv.z), f2tf32(vv.w) };
            *(uint4*)&Ksu[r * KPAD + c] = ku;
            *(uint4*)&Vsu[r * VPAD + c] = vu;
        }
        __syncthreads();

        // ---- S = Q K^T  (16 rows x 64 keys per warp) ----
        float s[8][4];
        #pragma unroll
        for (int nt = 0; nt < 8; nt++) {
            #pragma unroll
            for (int c = 0; c < 4; c++) s[nt][c] = 0.f;
            const int key = nt * 8 + g;
            #pragma unroll
            for (int ks = 0; ks < 8; ks++) {
                const int d = ks * 8 + tig;
                uint32_t b0 = Ksu[key * KPAD + d];
                uint32_t b1 = Ksu[key * KPAD + d + 4];
                mma_tf32(s[nt], qf[ks][0], qf[ks][1], qf[ks][2], qf[ks][3], b0, b1);
            }
        }

        // ---- online softmax (rows row_a = g, row_b = g+8; base-2) ----
        float t0 = -1e30f, t1 = -1e30f;
        #pragma unroll
        for (int nt = 0; nt < 8; nt++) {
            t0 = fmaxf(t0, fmaxf(s[nt][0], s[nt][1]));
            t1 = fmaxf(t1, fmaxf(s[nt][2], s[nt][3]));
        }
        t0 = fmaxf(t0, __shfl_xor_sync(0xffffffffu, t0, 1));
        t0 = fmaxf(t0, __shfl_xor_sync(0xffffffffu, t0, 2));
        t1 = fmaxf(t1, __shfl_xor_sync(0xffffffffu, t1, 1));
        t1 = fmaxf(t1, __shfl_xor_sync(0xffffffffu, t1, 2));
        const float nm0 = fmaxf(m0, t0), nm1 = fmaxf(m1, t1);
        const float cr0 = fexp2(m0 - nm0), cr1 = fexp2(m1 - nm1);

        float p0 = 0.f, p1 = 0.f;
        #pragma unroll
        for (int nt = 0; nt < 8; nt++) {
            s[nt][0] = fexp2(s[nt][0] - nm0);
            s[nt][1] = fexp2(s[nt][1] - nm0);
            s[nt][2] = fexp2(s[nt][2] - nm1);
            s[nt][3] = fexp2(s[nt][3] - nm1);
            p0 += s[nt][0] + s[nt][1];
            p1 += s[nt][2] + s[nt][3];
        }
        p0 += __shfl_xor_sync(0xffffffffu, p0, 1);
        p0 += __shfl_xor_sync(0xffffffffu, p0, 2);
        p1 += __shfl_xor_sync(0xffffffffu, p1, 1);
        p1 += __shfl_xor_sync(0xffffffffu, p1, 2);
        l0 = l0 * cr0 + p0;
        l1 = l1 * cr1 + p1;
        m0 = nm0; m1 = nm1;

        #pragma unroll
        for (int nt = 0; nt < 8; nt++) {
            o[nt][0] *= cr0; o[nt][1] *= cr0;
            o[nt][2] *= cr1; o[nt][3] *= cr1;
        }

        // ---- P -> per-warp smem (tf32-converted), re-fragment for PV ----
        #pragma unroll
        for (int nt = 0; nt < 8; nt++) {
            const int col = nt * 8 + 2 * tig;
            float2 lo = { __uint_as_float(f2tf32(s[nt][0])),
                          __uint_as_float(f2tf32(s[nt][1])) };
            float2 hi = { __uint_as_float(f2tf32(s[nt][2])),
                          __uint_as_float(f2tf32(s[nt][3])) };
            *(float2*)&Pw[g * PPAD + col]       = lo;
            *(float2*)&Pw[(g + 8) * PPAD + col] = hi;
        }
        __syncwarp();

        // A fragments of P: depend only on key-chunk ks (hoisted out of nt loop)
        uint32_t af[8][4];
        #pragma unroll
        for (int ks = 0; ks < 8; ks++) {
            const int kk = ks * 8 + tig;
            af[ks][0] = __float_as_uint(Pw[g * PPAD + kk]);
            af[ks][1] = __float_as_uint(Pw[(g + 8) * PPAD + kk]);
            af[ks][2] = __float_as_uint(Pw[g * PPAD + kk + 4]);
            af[ks][3] = __float_as_uint(Pw[(g + 8) * PPAD + kk + 4]);
        }

        // ---- O += P V ----
        #pragma unroll
        for (int nt = 0; nt < 8; nt++) {
            const int dcol = nt * 8 + g;
            #pragma unroll
            for (int ks = 0; ks < 8; ks++) {
                const int key = ks * 8 + tig;
                uint32_t b0 = Vsu[key * VPAD + dcol];
                uint32_t b1 = Vsu[(key + 4) * VPAD + dcol];
                mma_tf32(o[nt], af[ks][0], af[ks][1], af[ks][2], af[ks][3], b0, b1);
            }
        }
        __syncthreads();
    }

    // ---- epilogue: normalize, write to g_ao ----
    const float inv0 = 1.0f / l0, inv1 = 1.0f / l1;
    float* oa = g_ao + (size_t)(b * SEQ + row_a) * D_MODEL + h * DK;
    float* ob = oa + (size_t)8 * D_MODEL;
    #pragma unroll
    for (int nt = 0; nt < 8; nt++) {
        const int col = nt * 8 + 2 * tig;
        float2 lo = { o[nt][0] * inv0, o[nt][1] * inv0 };
        float2 hi = { o[nt][2] * inv1, o[nt][3] * inv1 };
        *(float2*)&oa[col] = lo;
        *(float2*)&ob[col] = hi;
    }
}

#define ATTN_SMEM_BYTES ((64*KPAD + 64*VPAD + 8*16*PPAD) * 4)  // 70656

extern "C" void kernel_launch(void* const* d_in, const int* in_sizes, int n_in,
                              void* d_out, int out_size) {
    const float* q  = (const float*)d_in[0];
    const float* k  = (const float*)d_in[1];
    const float* v  = (const float*)d_in[2];
    const float* Wq = (const float*)d_in[3];
    const float* bq = (const float*)d_in[4];
    const float* Wk = (const float*)d_in[5];
    const float* bk = (const float*)d_in[6];
    const float* Wv = (const float*)d_in[7];
    const float* bv = (const float*)d_in[8];
    const float* Wo = (const float*)d_in[9];
    const float* bo = (const float*)d_in[10];
    float* out = (float*)d_out;

    cudaFuncSetAttribute(flash_attn_tc,
                         cudaFuncAttributeMaxDynamicSharedMemorySize,
                         ATTN_SMEM_BYTES);

    dim3 gp(MTOT / BM, D_MODEL / BN);     // 64 x 12
    gemm_bias_kernel<<<gp, 256>>>(q, Wq, bq, nullptr, 0);
    gemm_bias_kernel<<<gp, 256>>>(k, Wk, bk, nullptr, 1);
    gemm_bias_kernel<<<gp, 256>>>(v, Wv, bv, nullptr, 2);

    dim3 ga(SEQ / 128, NHEADS, BATCH);    // 16 x 12 x 2
    flash_attn_tc<<<ga, 256, ATTN_SMEM_BYTES>>>();

    gemm_bias_kernel<<<gp, 256>>>(nullptr, Wo, bo, out, 3);
}

// round 6
// speedup vs baseline: 4.8675x; 1.4237x over previous
#include <cuda_runtime.h>
#include <cstdint>

#define D_MODEL 768
#define NHEADS  12
#define DK      64
#define BATCH   2
#define SEQ     2048
#define MTOT    (BATCH*SEQ)   // 4096

// Scratch (device globals: allocation-free, harness-safe)
__device__ float g_q [BATCH*NHEADS*SEQ*DK];   // [B,H,S,dk]
__device__ float g_k [BATCH*NHEADS*SEQ*DK];
__device__ float g_v [BATCH*NHEADS*SEQ*DK];
__device__ float g_ao[MTOT*D_MODEL];          // [B,S,D] attention output

__device__ __forceinline__ uint32_t f2tf32(float x) {
    uint32_t r;
    asm("cvt.rna.tf32.f32 %0, %1;" : "=r"(r) : "f"(x));
    return r;
}
__device__ __forceinline__ float fexp2(float x) {
    float y;
    asm("ex2.approx.ftz.f32 %0, %1;" : "=f"(y) : "f"(x));
    return y;
}
__device__ __forceinline__ void mma_tf32(float c[4],
        uint32_t a0, uint32_t a1, uint32_t a2, uint32_t a3,
        uint32_t b0, uint32_t b1) {
    asm volatile(
        "mma.sync.aligned.m16n8k8.row.col.f32.tf32.tf32.f32 "
        "{%0,%1,%2,%3}, {%4,%5,%6,%7}, {%8,%9}, {%0,%1,%2,%3};"
        : "+f"(c[0]), "+f"(c[1]), "+f"(c[2]), "+f"(c[3])
        : "r"(a0), "r"(a1), "r"(a2), "r"(a3), "r"(b0), "r"(b1));
}

// ---------------------------------------------------------------------------
// 3xTF32 tensor-core GEMM with bias (fp32-accurate).
// Block: 128(M) x 64(N), BK=32. 8 warps in 4(m) x 2(n); warp tile 32x32.
// mode 0/1/2: scatter into g_q/g_k/g_v head-split. mode 3: row-major outp.
// A==nullptr -> read from g_ao.
// ---------------------------------------------------------------------------
#define GM 128
#define GN 64
#define GK 32
#define APAD 36   // (4g+tig)%32 distinct -> conflict-free A frags
#define BPAD 72   // (8tig+g)%32 distinct -> conflict-free B frags
#define GEMM_SMEM ((2*128*APAD + 2*GK*BPAD) * 4)   // 55296 B

__global__ __launch_bounds__(256, 2) void gemm_tc(
        const float* __restrict__ A, const float* __restrict__ W,
        const float* __restrict__ bias, float* __restrict__ outp, int mode) {
    extern __shared__ float sm[];
    float* Ah = sm;                  // [128][APAD]
    float* Al = Ah + 128 * APAD;
    float* Bh = Al + 128 * APAD;     // [GK][BPAD]
    float* Bl = Bh + GK * BPAD;

    const float* __restrict__ Ain = A ? A : (const float*)g_ao;
    const int m0 = blockIdx.x * GM, n0 = blockIdx.y * GN;
    const int t = threadIdx.x, warp = t >> 5, lane = t & 31;
    const int g = lane >> 2, tig = lane & 3;
    const int wm = (warp & 3) * 32, wn = (warp >> 2) * 32;

    const int am = t >> 3, ak = (t & 7) * 4;   // A stage: rows am+32i, k ak..ak+3
    const int bk = t >> 4, bn = (t & 15) * 4;  // B stage: k bk+16i, n bn..bn+3

    // prefetch tile 0 into registers
    float4 aS[4], bS[2];
    #pragma unroll
    for (int i = 0; i < 4; i++)
        aS[i] = *(const float4*)&Ain[(size_t)(m0 + am + i*32) * D_MODEL + ak];
    #pragma unroll
    for (int i = 0; i < 2; i++)
        bS[i] = *(const float4*)&W[(size_t)(bk + i*16) * D_MODEL + n0 + bn];

    float acc[2][4][4] = {};

    for (int kt = 0; kt < D_MODEL / GK; kt++) {
        // ---- stage -> smem with hi/lo tf32 split ----
        #pragma unroll
        for (int i = 0; i < 4; i++) {
            float4 v = aS[i], h, l;
            h.x = __uint_as_float(f2tf32(v.x)); l.x = __uint_as_float(f2tf32(v.x - h.x));
            h.y = __uint_as_float(f2tf32(v.y)); l.y = __uint_as_float(f2tf32(v.y - h.y));
            h.z = __uint_as_float(f2tf32(v.z)); l.z = __uint_as_float(f2tf32(v.z - h.z));
            h.w = __uint_as_float(f2tf32(v.w)); l.w = __uint_as_float(f2tf32(v.w - h.w));
            *(float4*)&Ah[(am + i*32) * APAD + ak] = h;
            *(float4*)&Al[(am + i*32) * APAD + ak] = l;
        }
        #pragma unroll
        for (int i = 0; i < 2; i++) {
            float4 v = bS[i], h, l;
            h.x = __uint_as_float(f2tf32(v.x)); l.x = __uint_as_float(f2tf32(v.x - h.x));
            h.y = __uint_as_float(f2tf32(v.y)); l.y = __uint_as_float(f2tf32(v.y - h.y));
            h.z = __uint_as_float(f2tf32(v.z)); l.z = __uint_as_float(f2tf32(v.z - h.z));
            h.w = __uint_as_float(f2tf32(v.w)); l.w = __uint_as_float(f2tf32(v.w - h.w));
            *(float4*)&Bh[(bk + i*16) * BPAD + bn] = h;
            *(float4*)&Bl[(bk + i*16) * BPAD + bn] = l;
        }
        __syncthreads();

        // ---- prefetch next tile (overlaps with mma work) ----
        if (kt + 1 < D_MODEL / GK) {
            const int k0 = (kt + 1) * GK;
            #pragma unroll
            for (int i = 0; i < 4; i++)
                aS[i] = *(const float4*)&Ain[(size_t)(m0 + am + i*32) * D_MODEL + k0 + ak];
            #pragma unroll
            for (int i = 0; i < 2; i++)
                bS[i] = *(const float4*)&W[(size_t)(k0 + bk + i*16) * D_MODEL + n0 + bn];
        }

        // ---- 3xTF32 mma over this k-tile ----
        #pragma unroll
        for (int kk = 0; kk < 4; kk++) {
            uint32_t afh[2][4], afl[2][4];
            #pragma unroll
            for (int mi = 0; mi < 2; mi++) {
                const int r0 = (wm + mi*16 + g) * APAD + kk*8 + tig;
                const int r1 = r0 + 8 * APAD;
                afh[mi][0] = __float_as_uint(Ah[r0]);
                afh[mi][1] = __float_as_uint(Ah[r1]);
                afh[mi][2] = __float_as_uint(Ah[r0 + 4]);
                afh[mi][3] = __float_as_uint(Ah[r1 + 4]);
                afl[mi][0] = __float_as_uint(Al[r0]);
                afl[mi][1] = __float_as_uint(Al[r1]);
                afl[mi][2] = __float_as_uint(Al[r0 + 4]);
                afl[mi][3] = __float_as_uint(Al[r1 + 4]);
            }
            uint32_t bfh[4][2], bfl[4][2];
            #pragma unroll
            for (int nt = 0; nt < 4; nt++) {
                const int r = (kk*8 + tig) * BPAD + wn + nt*8 + g;
                bfh[nt][0] = __float_as_uint(Bh[r]);
                bfh[nt][1] = __float_as_uint(Bh[r + 4*BPAD]);
                bfl[nt][0] = __float_as_uint(Bl[r]);
                bfl[nt][1] = __float_as_uint(Bl[r + 4*BPAD]);
            }
            #pragma unroll
            for (int mi = 0; mi < 2; mi++)
                #pragma unroll
                for (int nt = 0; nt < 4; nt++) {
                    mma_tf32(acc[mi][nt], afh[mi][0], afh[mi][1], afh[mi][2], afh[mi][3],
                             bfh[nt][0], bfh[nt][1]);
                    mma_tf32(acc[mi][nt], afh[mi][0], afh[mi][1], afh[mi][2], afh[mi][3],
                             bfl[nt][0], bfl[nt][1]);
                    mma_tf32(acc[mi][nt], afl[mi][0], afl[mi][1], afl[mi][2], afl[mi][3],
                             bfh[nt][0], bfh[nt][1]);
                }
        }
        __syncthreads();
    }

    // ---- epilogue: bias + write (row-major or head-split scatter) ----
    #pragma unroll
    for (int mi = 0; mi < 2; mi++) {
        #pragma unroll
        for (int nt = 0; nt < 4; nt++) {
            const int col = wn + nt*8 + 2*tig;           // 0..62 within N-tile
            const float b0 = bias[n0 + col];
            const float b1 = bias[n0 + col + 1];
            const int mA = m0 + wm + mi*16 + g;
            const int mB = mA + 8;
            float2 vA = { acc[mi][nt][0] + b0, acc[mi][nt][1] + b1 };
            float2 vB = { acc[mi][nt][2] + b0, acc[mi][nt][3] + b1 };
            if (mode == 3) {
                *(float2*)&outp[(size_t)mA * D_MODEL + n0 + col] = vA;
                *(float2*)&outp[(size_t)mB * D_MODEL + n0 + col] = vB;
            } else {
                float* o = (mode == 0) ? g_q : (mode == 1) ? g_k : g_v;
                const int h = n0 >> 6;                    // N-tile == one head
                const size_t iA = (((size_t)((mA >> 11) * NHEADS + h) * SEQ)
                                   + (mA & 2047)) * DK + col;
                const size_t iB = (((size_t)((mB >> 11) * NHEADS + h) * SEQ)
                                   + (mB & 2047)) * DK + col;
                *(float2*)&o[iA] = vA;
                *(float2*)&o[iB] = vB;
            }
        }
    }
}

// ---------------------------------------------------------------------------
// Tensor-core (tf32 HMMA) flash attention — unchanged from R3 (286us, proven)
// Block: 128 queries of one (b,h); 8 warps, each warp owns 16 query rows.
// ---------------------------------------------------------------------------
#define KPAD 68
#define VPAD 72
#define PPAD 68

__global__ __launch_bounds__(256) void flash_attn_tc() {
    extern __shared__ uint32_t smem_u[];
    uint32_t* Ksu = smem_u;                       // [64][KPAD]
    uint32_t* Vsu = smem_u + 64 * KPAD;           // [64][VPAD]
    float*    Psb = (float*)(smem_u + 64 * KPAD + 64 * VPAD); // 8 x [16][PPAD]

    const int t    = threadIdx.x;
    const int warp = t >> 5;
    const int lane = t & 31;
    const int g    = lane >> 2;
    const int tig  = lane & 3;

    const int qt = blockIdx.x, h = blockIdx.y, b = blockIdx.z;
    const size_t headBase = (size_t)(b * NHEADS + h) * SEQ * DK;
    const float* __restrict__ kp = g_k + headBase;
    const float* __restrict__ vp = g_v + headBase;

    const float qscale = 0.125f * 1.4426950408889634f;
    const int row_a = qt * 128 + warp * 16 + g;
    const float* __restrict__ qa = g_q + headBase + (size_t)row_a * DK;
    const float* __restrict__ qb = qa + 8 * DK;

    uint32_t qf[8][4];
    #pragma unroll
    for (int ks = 0; ks < 8; ks++) {
        const int c0 = 8 * ks + tig;
        qf[ks][0] = f2tf32(qa[c0]     * qscale);
        qf[ks][1] = f2tf32(qb[c0]     * qscale);
        qf[ks][2] = f2tf32(qa[c0 + 4] * qscale);
        qf[ks][3] = f2tf32(qb[c0 + 4] * qscale);
    }

    float o[8][4];
    #pragma unroll
    for (int nt = 0; nt < 8; nt++)
        #pragma unroll
        for (int c = 0; c < 4; c++) o[nt][c] = 0.f;
    float m0 = -1e30f, m1 = -1e30f, l0 = 0.f, l1 = 0.f;

    float* Pw = Psb + warp * 16 * PPAD;

    for (int k0 = 0; k0 < SEQ; k0 += 64) {
        #pragma unroll
        for (int i = 0; i < 4; i++) {
            const int fi = t + i * 256;
            const int r  = fi >> 4;
            const int c  = (fi & 15) * 4;
            float4 kv = *(const float4*)&kp[(size_t)(k0 + r) * DK + c];
            float4 vv = *(const float4*)&vp[(size_t)(k0 + r) * DK + c];
            uint4 ku = { f2tf32(kv.x), f2tf32(kv.y), f2tf32(kv.z), f2tf32(kv.w) };
            uint4 vu = { f2tf32(vv.x), f2tf32(vv.y), f2tf32(vv.z), f2tf32(vv.w) };
            *(uint4*)&Ksu[r * KPAD + c] = ku;
            *(uint4*)&Vsu[r * VPAD + c] = vu;
        }
        __syncthreads();

        float s[8][4];
        #pragma unroll
        for (int nt = 0; nt < 8; nt++) {
            #pragma unroll
            for (int c = 0; c < 4; c++) s[nt][c] = 0.f;
            const int key = nt * 8 + g;
            #pragma unroll
            for (int ks = 0; ks < 8; ks++) {
                const int d = ks * 8 + tig;
                uint32_t b0 = Ksu[key * KPAD + d];
                uint32_t b1 = Ksu[key * KPAD + d + 4];
                mma_tf32(s[nt], qf[ks][0], qf[ks][1], qf[ks][2], qf[ks][3], b0, b1);
            }
        }

        float t0 = -1e30f, t1 = -1e30f;
        #pragma unroll
        for (int nt = 0; nt < 8; nt++) {
            t0 = fmaxf(t0, fmaxf(s[nt][0], s[nt][1]));
            t1 = fmaxf(t1, fmaxf(s[nt][2], s[nt][3]));
        }
        t0 = fmaxf(t0, __shfl_xor_sync(0xffffffffu, t0, 1));
        t0 = fmaxf(t0, __shfl_xor_sync(0xffffffffu, t0, 2));
        t1 = fmaxf(t1, __shfl_xor_sync(0xffffffffu, t1, 1));
        t1 = fmaxf(t1, __shfl_xor_sync(0xffffffffu, t1, 2));
        const float nm0 = fmaxf(m0, t0), nm1 = fmaxf(m1, t1);
        const float cr0 = fexp2(m0 - nm0), cr1 = fexp2(m1 - nm1);

        float p0 = 0.f, p1 = 0.f;
        #pragma unroll
        for (int nt = 0; nt < 8; nt++) {
            s[nt][0] = fexp2(s[nt][0] - nm0);
            s[nt][1] = fexp2(s[nt][1] - nm0);
            s[nt][2] = fexp2(s[nt][2] - nm1);
            s[nt][3] = fexp2(s[nt][3] - nm1);
            p0 += s[nt][0] + s[nt][1];
            p1 += s[nt][2] + s[nt][3];
        }
        p0 += __shfl_xor_sync(0xffffffffu, p0, 1);
        p0 += __shfl_xor_sync(0xffffffffu, p0, 2);
        p1 += __shfl_xor_sync(0xffffffffu, p1, 1);
        p1 += __shfl_xor_sync(0xffffffffu, p1, 2);
        l0 = l0 * cr0 + p0;
        l1 = l1 * cr1 + p1;
        m0 = nm0; m1 = nm1;

        #pragma unroll
        for (int nt = 0; nt < 8; nt++) {
            o[nt][0] *= cr0; o[nt][1] *= cr0;
            o[nt][2] *= cr1; o[nt][3] *= cr1;
        }

        #pragma unroll
        for (int nt = 0; nt < 8; nt++) {
            const int col = nt * 8 + 2 * tig;
            float2 lo = { __uint_as_float(f2tf32(s[nt][0])),
                          __uint_as_float(f2tf32(s[nt][1])) };
            float2 hi = { __uint_as_float(f2tf32(s[nt][2])),
                          __uint_as_float(f2tf32(s[nt][3])) };
            *(float2*)&Pw[g * PPAD + col]       = lo;
            *(float2*)&Pw[(g + 8) * PPAD + col] = hi;
        }
        __syncwarp();

        uint32_t af[8][4];
        #pragma unroll
        for (int ks = 0; ks < 8; ks++) {
            const int kk = ks * 8 + tig;
            af[ks][0] = __float_as_uint(Pw[g * PPAD + kk]);
            af[ks][1] = __float_as_uint(Pw[(g + 8) * PPAD + kk]);
            af[ks][2] = __float_as_uint(Pw[g * PPAD + kk + 4]);
            af[ks][3] = __float_as_uint(Pw[(g + 8) * PPAD + kk + 4]);
        }

        #pragma unroll
        for (int nt = 0; nt < 8; nt++) {
            const int dcol = nt * 8 + g;
            #pragma unroll
            for (int ks = 0; ks < 8; ks++) {
                const int key = ks * 8 + tig;
                uint32_t b0 = Vsu[key * VPAD + dcol];
                uint32_t b1 = Vsu[(key + 4) * VPAD + dcol];
                mma_tf32(o[nt], af[ks][0], af[ks][1], af[ks][2], af[ks][3], b0, b1);
            }
        }
        __syncthreads();
    }

    const float inv0 = 1.0f / l0, inv1 = 1.0f / l1;
    float* oa = g_ao + (size_t)(b * SEQ + row_a) * D_MODEL + h * DK;
    float* ob = oa + (size_t)8 * D_MODEL;
    #pragma unroll
    for (int nt = 0; nt < 8; nt++) {
        const int col = nt * 8 + 2 * tig;
        float2 lo = { o[nt][0] * inv0, o[nt][1] * inv0 };
        float2 hi = { o[nt][2] * inv1, o[nt][3] * inv1 };
        *(float2*)&oa[col] = lo;
        *(float2*)&ob[col] = hi;
    }
}

#define ATTN_SMEM_BYTES ((64*KPAD + 64*VPAD + 8*16*PPAD) * 4)  // 70656

extern "C" void kernel_launch(void* const* d_in, const int* in_sizes, int n_in,
                              void* d_out, int out_size) {
    const float* q  = (const float*)d_in[0];
    const float* k  = (const float*)d_in[1];
    const float* v  = (const float*)d_in[2];
    const float* Wq = (const float*)d_in[3];
    const float* bq = (const float*)d_in[4];
    const float* Wk = (const float*)d_in[5];
    const float* bk = (const float*)d_in[6];
    const float* Wv = (const float*)d_in[7];
    const float* bv = (const float*)d_in[8];
    const float* Wo = (const float*)d_in[9];
    const float* bo = (const float*)d_in[10];
    float* out = (float*)d_out;

    cudaFuncSetAttribute(gemm_tc,
                         cudaFuncAttributeMaxDynamicSharedMemorySize,
                         GEMM_SMEM);
    cudaFuncSetAttribute(flash_attn_tc,
                         cudaFuncAttributeMaxDynamicSharedMemorySize,
                         ATTN_SMEM_BYTES);

    dim3 gg(MTOT / GM, D_MODEL / GN);     // 32 x 12
    gemm_tc<<<gg, 256, GEMM_SMEM>>>(q, Wq, bq, nullptr, 0);
    gemm_tc<<<gg, 256, GEMM_SMEM>>>(k, Wk, bk, nullptr, 1);
    gemm_tc<<<gg, 256, GEMM_SMEM>>>(v, Wv, bv, nullptr, 2);

    dim3 ga(SEQ / 128, NHEADS, BATCH);    // 16 x 12 x 2
    flash_attn_tc<<<ga, 256, ATTN_SMEM_BYTES>>>();

    gemm_tc<<<gg, 256, GEMM_SMEM>>>(nullptr, Wo, bo, out, 3);
}